// round 1
// baseline (speedup 1.0000x reference)
#include <cuda_runtime.h>

#define BB 16
#define CC 256
#define HW 3136
#define CI 32
#define CG 64
#define NP 784
#define OUTC 128   /* theta(32) | g(64) | phi(32) */
#define EPSI 1e-5f

// ---------------- scratch (static __device__, no allocation) ----------------
__device__ float d_conv[(size_t)BB*OUTC*HW];   // fused conv output (theta rows 0..31, g 32..95, phi 96..127)
__device__ float d_gpool[BB*CG*NP];
__device__ float d_phipool[BB*CI*NP];
__device__ float d_M[BB*CI*CG];
__device__ float d_y[(size_t)BB*CG*HW];
__device__ float d_WcT[CC*OUTC];               // combined conv weight, k-major [k][o]
__device__ float d_bc[OUTC];
__device__ float d_WzT[CG*CC];                 // w_z, k-major [k][o]
__device__ float d_s1[CC], d_t1[CC];
__device__ float d_s2[CG], d_t2[CG];
__device__ float d_ysum[CG], d_ysumsq[CG];

// ---------------- packed f32x2 helpers ----------------
__device__ __forceinline__ unsigned long long pk2(float lo, float hi) {
    unsigned long long r;
    asm("mov.b64 %0, {%1, %2};" : "=l"(r) : "f"(lo), "f"(hi));
    return r;
}
__device__ __forceinline__ void fma2(unsigned long long& d, unsigned long long a, unsigned long long b) {
    asm("fma.rn.f32x2 %0, %1, %2, %0;" : "+l"(d) : "l"(a), "l"(b));
}
__device__ __forceinline__ float2 upk2(unsigned long long v) {
    float lo, hi;
    asm("mov.b64 {%0, %1}, %2;" : "=f"(lo), "=f"(hi) : "l"(v));
    return make_float2(lo, hi);
}

// ---------------- K0: prep (weight transposes, zero accumulators) ----------------
__global__ void k_prep(const float* __restrict__ wg, const float* __restrict__ wth,
                       const float* __restrict__ wphi, const float* __restrict__ wz,
                       const float* __restrict__ bg, const float* __restrict__ bth,
                       const float* __restrict__ bphi) {
    int idx = blockIdx.x * 256 + threadIdx.x;
    if (idx < CC * OUTC) {
        int k = idx / OUTC, o = idx % OUTC;
        float w;
        if (o < 32)      w = wth[o * CC + k];
        else if (o < 96) w = wg[(o - 32) * CC + k];
        else             w = wphi[(o - 96) * CC + k];
        d_WcT[idx] = w;
    }
    int j = idx - CC * OUTC;
    if (j >= 0 && j < CG * CC) {
        int k = j / CC, o = j % CC;
        d_WzT[j] = wz[o * CG + k];
    }
    int l = idx - CC * OUTC - CG * CC;
    if (l >= 0 && l < OUTC)
        d_bc[l] = (l < 32) ? bth[l] : (l < 96 ? bg[l - 32] : bphi[l - 96]);
    if (l >= OUTC && l < OUTC + CG) {
        int c = l - OUTC;
        d_ysum[c] = 0.f; d_ysumsq[c] = 0.f;
    }
    int m = l - OUTC - CG;
    if (m >= 0 && m < BB * CI * CG) d_M[m] = 0.f;
}

// ---------------- K1: BN1 stats (one block per channel) ----------------
__global__ void __launch_bounds__(256) k_bn1(const float* __restrict__ x,
                                             const float* __restrict__ g1,
                                             const float* __restrict__ b1) {
    int c = blockIdx.x;
    float s = 0.f, ss = 0.f;
    for (int b = 0; b < BB; b++) {
        const float4* p = (const float4*)(x + (size_t)(b * CC + c) * HW);
        for (int i = threadIdx.x; i < HW / 4; i += 256) {
            float4 v = p[i];
            s  += v.x + v.y + v.z + v.w;
            ss += v.x * v.x + v.y * v.y + v.z * v.z + v.w * v.w;
        }
    }
    for (int off = 16; off; off >>= 1) {
        s  += __shfl_down_sync(0xffffffffu, s, off);
        ss += __shfl_down_sync(0xffffffffu, ss, off);
    }
    __shared__ float rs[8], rss[8];
    int wid = threadIdx.x >> 5, lane = threadIdx.x & 31;
    if (lane == 0) { rs[wid] = s; rss[wid] = ss; }
    __syncthreads();
    if (threadIdx.x == 0) {
        float S = 0.f, SS = 0.f;
        for (int i = 0; i < 8; i++) { S += rs[i]; SS += rss[i]; }
        float n = (float)(BB * HW);
        float mean = S / n;
        float var = SS / n - mean * mean;
        float rstd = rsqrtf(var + EPSI);
        float sc = g1[c] * rstd;
        d_s1[c] = sc;
        d_t1[c] = b1[c] - mean * sc;
    }
}

// ---------------- K2: fused BN1+ReLU+3xconv1x1 (128x64 tile GEMM, K=256) ----------------
__global__ void __launch_bounds__(256) k_fconv(const float* __restrict__ x) {
    int b = blockIdx.y;
    int p0 = blockIdx.x * 64;
    __shared__ float Ws[32 * 128];
    __shared__ float Xs[32 * 64];
    int tid = threadIdx.x;
    int tx = tid & 15, ty = tid >> 4;        // pix base tx*4, out base ty*8
    unsigned long long acc[8][2];
#pragma unroll
    for (int oi = 0; oi < 8; oi++) { acc[oi][0] = 0ull; acc[oi][1] = 0ull; }

    for (int k0 = 0; k0 < CC; k0 += 32) {
        __syncthreads();
        {   // weights: contiguous copy of WcT rows k0..k0+31
            const float4* src = (const float4*)(d_WcT + k0 * OUTC);
            float4* dst = (float4*)Ws;
#pragma unroll
            for (int j = 0; j < 4; j++) dst[tid + j * 256] = src[tid + j * 256];
        }
        // x chunk: normalize + relu on the fly
#pragma unroll
        for (int j = 0; j < 2; j++) {
            int idx = tid + j * 256;
            int kk = idx >> 4, f4i = idx & 15;
            int c = k0 + kk;
            float4 v = *(const float4*)(x + (size_t)(b * CC + c) * HW + p0 + f4i * 4);
            float sc = d_s1[c], sh = d_t1[c];
            v.x = fmaxf(fmaf(v.x, sc, sh), 0.f);
            v.y = fmaxf(fmaf(v.y, sc, sh), 0.f);
            v.z = fmaxf(fmaf(v.z, sc, sh), 0.f);
            v.w = fmaxf(fmaf(v.w, sc, sh), 0.f);
            *(float4*)(Xs + kk * 64 + f4i * 4) = v;
        }
        __syncthreads();
#pragma unroll 4
        for (int k = 0; k < 32; k++) {
            float4 w0 = *(float4*)(Ws + k * 128 + ty * 8);
            float4 w1 = *(float4*)(Ws + k * 128 + ty * 8 + 4);
            float4 xv = *(float4*)(Xs + k * 64 + tx * 4);
            unsigned long long x01 = pk2(xv.x, xv.y), x23 = pk2(xv.z, xv.w);
            float wv[8] = {w0.x, w0.y, w0.z, w0.w, w1.x, w1.y, w1.z, w1.w};
#pragma unroll
            for (int oi = 0; oi < 8; oi++) {
                unsigned long long wd = pk2(wv[oi], wv[oi]);
                fma2(acc[oi][0], wd, x01);
                fma2(acc[oi][1], wd, x23);
            }
        }
    }
#pragma unroll
    for (int oi = 0; oi < 8; oi++) {
        int o = ty * 8 + oi;
        float bias = d_bc[o];
        float2 a = upk2(acc[oi][0]), c2 = upk2(acc[oi][1]);
        float4 out = make_float4(a.x + bias, a.y + bias, c2.x + bias, c2.y + bias);
        *(float4*)(d_conv + (size_t)(b * OUTC + o) * HW + p0 + tx * 4) = out;
    }
}

// ---------------- K3: 2x2 maxpool of g/phi ----------------
__global__ void k_pool() {
    int idx = blockIdx.x * 256 + threadIdx.x;
    if (idx >= BB * 96 * NP) return;
    int b = idx / (96 * NP);
    int r = idx % (96 * NP);
    int ch = r / NP;
    int pp = r % NP;
    int ph = pp / 28, pw = pp % 28;
    const float* src = d_conv + (size_t)(b * OUTC + 32 + ch) * HW + ph * 112 + pw * 2;
    float v = fmaxf(fmaxf(src[0], src[1]), fmaxf(src[56], src[57]));
    if (ch < 64) d_gpool[(b * CG + ch) * NP + pp] = v;
    else         d_phipool[(b * CI + (ch - 64)) * NP + pp] = v;
}

// ---------------- K4: M[b] = phi_pool @ g_pool^T (32x64 per batch) ----------------
__global__ void __launch_bounds__(512) k_M() {
    int b = blockIdx.y;
    int m0 = blockIdx.x * 112;
    __shared__ float Ps[CI][113];
    __shared__ float Gs[CG][113];
    int tid = threadIdx.x;
    for (int j = tid; j < CI * 112; j += 512) {
        int i = j / 112, mm = j % 112;
        Ps[i][mm] = d_phipool[(b * CI + i) * NP + m0 + mm];
    }
    for (int j = tid; j < CG * 112; j += 512) {
        int i = j / 112, mm = j % 112;
        Gs[i][mm] = d_gpool[(b * CG + i) * NP + m0 + mm];
    }
    __syncthreads();
#pragma unroll
    for (int q = 0; q < 4; q++) {
        int o = tid + q * 512;
        int i = o >> 6, c = o & 63;
        float acc = 0.f;
#pragma unroll 8
        for (int mm = 0; mm < 112; mm++) acc = fmaf(Ps[i][mm], Gs[c][mm], acc);
        atomicAdd(&d_M[(b * CI + i) * CG + c], acc);
    }
}

// ---------------- K5: y = (M/Np)^T @ theta, fused BN2-stat accumulation ----------------
__global__ void __launch_bounds__(256) k_Y() {
    int b = blockIdx.y;
    int p0 = blockIdx.x * 64;
    __shared__ float Ms[CI * CG];
    __shared__ float Ts[CI * 64];
    __shared__ float bs[CG], bss[CG];
    int tid = threadIdx.x;
    const float invNp = 1.0f / (float)NP;
    for (int j = tid; j < CI * CG; j += 256) Ms[j] = d_M[b * CI * CG + j] * invNp;
    for (int j = tid; j < CI * 64; j += 256) {
        int i = j >> 6, col = j & 63;
        Ts[j] = d_conv[(size_t)(b * OUTC + i) * HW + p0 + col];
    }
    if (tid < CG) { bs[tid] = 0.f; bss[tid] = 0.f; }
    __syncthreads();
    int tx = tid & 15, ty = tid >> 4;        // pix base tx*4, cg base ty*4
    unsigned long long acc[4][2];
#pragma unroll
    for (int ci = 0; ci < 4; ci++) { acc[ci][0] = 0ull; acc[ci][1] = 0ull; }
#pragma unroll 8
    for (int i = 0; i < CI; i++) {
        float4 mv = *(float4*)&Ms[i * CG + ty * 4];
        float4 tv = *(float4*)&Ts[i * 64 + tx * 4];
        unsigned long long t01 = pk2(tv.x, tv.y), t23 = pk2(tv.z, tv.w);
        float mm[4] = {mv.x, mv.y, mv.z, mv.w};
#pragma unroll
        for (int ci = 0; ci < 4; ci++) {
            unsigned long long md = pk2(mm[ci], mm[ci]);
            fma2(acc[ci][0], md, t01);
            fma2(acc[ci][1], md, t23);
        }
    }
#pragma unroll
    for (int ci = 0; ci < 4; ci++) {
        int cg = ty * 4 + ci;
        float2 a = upk2(acc[ci][0]), c2 = upk2(acc[ci][1]);
        *(float4*)(d_y + (size_t)(b * CG + cg) * HW + p0 + tx * 4) =
            make_float4(a.x, a.y, c2.x, c2.y);
        atomicAdd(&bs[cg], a.x + a.y + c2.x + c2.y);
        atomicAdd(&bss[cg], a.x * a.x + a.y * a.y + c2.x * c2.x + c2.y * c2.y);
    }
    __syncthreads();
    if (tid < CG) {
        atomicAdd(&d_ysum[tid], bs[tid]);
        atomicAdd(&d_ysumsq[tid], bss[tid]);
    }
}

// ---------------- K5b: BN2 scale/shift ----------------
__global__ void k_bn2(const float* __restrict__ g2, const float* __restrict__ b2) {
    int c = threadIdx.x;
    if (c < CG) {
        float n = (float)(BB * HW);
        float mean = d_ysum[c] / n;
        float var = d_ysumsq[c] / n - mean * mean;
        float rstd = rsqrtf(var + EPSI);
        float sc = g2[c] * rstd;
        d_s2[c] = sc;
        d_t2[c] = b2[c] - mean * sc;
    }
}

// ---------------- K6: BN2+ReLU+conv(64->256)+bias+identity ----------------
__global__ void __launch_bounds__(256) k_final(const float* __restrict__ x,
                                               const float* __restrict__ bz,
                                               float* __restrict__ out) {
    int b = blockIdx.y;
    int p0 = blockIdx.x * 64;
    __shared__ float Wzs[32 * 256];
    __shared__ float Ys[32 * 64];
    int tid = threadIdx.x;
    int tx = tid & 7, ty = tid >> 3;         // pix base tx*8, out base ty*8
    unsigned long long acc[8][4];
#pragma unroll
    for (int oi = 0; oi < 8; oi++)
#pragma unroll
        for (int pj = 0; pj < 4; pj++) acc[oi][pj] = 0ull;

    for (int k0 = 0; k0 < CG; k0 += 32) {
        __syncthreads();
        {
            const float4* src = (const float4*)(d_WzT + k0 * CC);
            float4* dst = (float4*)Wzs;
#pragma unroll
            for (int j = 0; j < 8; j++) dst[tid + j * 256] = src[tid + j * 256];
        }
#pragma unroll
        for (int j = 0; j < 2; j++) {
            int idx = tid + j * 256;
            int kk = idx >> 4, f4i = idx & 15;
            int cg = k0 + kk;
            float4 v = *(const float4*)(d_y + (size_t)(b * CG + cg) * HW + p0 + f4i * 4);
            float sc = d_s2[cg], sh = d_t2[cg];
            v.x = fmaxf(fmaf(v.x, sc, sh), 0.f);
            v.y = fmaxf(fmaf(v.y, sc, sh), 0.f);
            v.z = fmaxf(fmaf(v.z, sc, sh), 0.f);
            v.w = fmaxf(fmaf(v.w, sc, sh), 0.f);
            *(float4*)(Ys + kk * 64 + f4i * 4) = v;
        }
        __syncthreads();
#pragma unroll 4
        for (int k = 0; k < 32; k++) {
            float4 w0 = *(float4*)(Wzs + k * 256 + ty * 8);
            float4 w1 = *(float4*)(Wzs + k * 256 + ty * 8 + 4);
            float4 y0 = *(float4*)(Ys + k * 64 + tx * 8);
            float4 y1 = *(float4*)(Ys + k * 64 + tx * 8 + 4);
            unsigned long long p01 = pk2(y0.x, y0.y), p23 = pk2(y0.z, y0.w);
            unsigned long long p45 = pk2(y1.x, y1.y), p67 = pk2(y1.z, y1.w);
            float wv[8] = {w0.x, w0.y, w0.z, w0.w, w1.x, w1.y, w1.z, w1.w};
#pragma unroll
            for (int oi = 0; oi < 8; oi++) {
                unsigned long long wd = pk2(wv[oi], wv[oi]);
                fma2(acc[oi][0], wd, p01);
                fma2(acc[oi][1], wd, p23);
                fma2(acc[oi][2], wd, p45);
                fma2(acc[oi][3], wd, p67);
            }
        }
    }
#pragma unroll
    for (int oi = 0; oi < 8; oi++) {
        int co = ty * 8 + oi;
        float bias = __ldg(&bz[co]);
        const float* xr = x + (size_t)(b * CC + co) * HW + p0 + tx * 8;
        float4 x0 = *(const float4*)xr;
        float4 x1 = *(const float4*)(xr + 4);
        float2 a0 = upk2(acc[oi][0]), a1 = upk2(acc[oi][1]);
        float2 a2 = upk2(acc[oi][2]), a3 = upk2(acc[oi][3]);
        float* orow = out + (size_t)(b * CC + co) * HW + p0 + tx * 8;
        *(float4*)orow = make_float4(a0.x + bias + x0.x, a0.y + bias + x0.y,
                                     a1.x + bias + x0.z, a1.y + bias + x0.w);
        *(float4*)(orow + 4) = make_float4(a2.x + bias + x1.x, a2.y + bias + x1.y,
                                           a3.x + bias + x1.z, a3.y + bias + x1.w);
    }
}

// ---------------- host ----------------
extern "C" void kernel_launch(void* const* d_in, const int* in_sizes, int n_in,
                              void* d_out, int out_size) {
    const float* x   = (const float*)d_in[0];
    const float* g1  = (const float*)d_in[1];
    const float* b1  = (const float*)d_in[2];
    const float* wg  = (const float*)d_in[3];
    const float* bg  = (const float*)d_in[4];
    const float* wth = (const float*)d_in[5];
    const float* bth = (const float*)d_in[6];
    const float* wph = (const float*)d_in[7];
    const float* bph = (const float*)d_in[8];
    const float* g2  = (const float*)d_in[9];
    const float* b2  = (const float*)d_in[10];
    const float* wz  = (const float*)d_in[11];
    const float* bz  = (const float*)d_in[12];
    float* out = (float*)d_out;

    int prep_elems = CC * OUTC + CG * CC + OUTC + CG + BB * CI * CG;
    k_prep<<<(prep_elems + 255) / 256, 256>>>(wg, wth, wph, wz, bg, bth, bph);
    k_bn1<<<CC, 256>>>(x, g1, b1);
    {
        dim3 g(HW / 64, BB);
        k_fconv<<<g, 256>>>(x);
    }
    k_pool<<<(BB * 96 * NP + 255) / 256, 256>>>();
    {
        dim3 g(7, BB);
        k_M<<<g, 512>>>();
    }
    {
        dim3 g(HW / 64, BB);
        k_Y<<<g, 256>>>();
    }
    k_bn2<<<1, 64>>>(g2, b2);
    {
        dim3 g(HW / 64, BB);
        k_final<<<g, 256>>>(x, bz, out);
    }
}

// round 3
// speedup vs baseline: 1.4172x; 1.4172x over previous
#include <cuda_runtime.h>
#include <cuda_bf16.h>
#include <cstdint>

#define BB 16
#define CC 256
#define HW 3136
#define CI 32
#define CG 64
#define NP 784
#define OUTC 128   /* theta(0..31) | g(32..95) | phi(96..127) */
#define EPSI 1e-5f

// ---------------- scratch ----------------
__device__ __align__(128) float d_conv[(size_t)BB*OUTC*HW];
__device__ __align__(128) float d_gpool[BB*CG*NP];
__device__ __align__(128) float d_phipool[BB*CI*NP];
__device__ __align__(128) float d_M[BB*CI*CG];
__device__ __align__(128) float d_y[(size_t)BB*CG*HW];
__device__ __align__(128) __nv_bfloat16 d_Wch[OUTC*CC];   // [128 o][256 k]
__device__ __align__(128) __nv_bfloat16 d_Wcl[OUTC*CC];
__device__ __align__(128) __nv_bfloat16 d_Wzh[CC*CG];     // [256 o][64 k]
__device__ __align__(128) __nv_bfloat16 d_Wzl[CC*CG];
__device__ float d_bc[OUTC];
__device__ float d_s1[CC], d_t1[CC];
__device__ float d_s2[CG], d_t2[CG];
__device__ float d_ysum[CG], d_ysumsq[CG];

// ---------------- helpers ----------------
#define SWZ128(off) ((off) ^ (((off) >> 3) & 0x70))

__device__ __forceinline__ uint32_t smem_u32(const void* p) {
    uint32_t a;
    asm("{ .reg .u64 t; cvta.to.shared.u64 t, %1; cvt.u32.u64 %0, t; }" : "=r"(a) : "l"(p));
    return a;
}
__device__ __forceinline__ void ldm_x4(uint32_t* r, uint32_t addr) {
    asm volatile("ldmatrix.sync.aligned.m8n8.x4.shared.b16 {%0,%1,%2,%3}, [%4];"
        : "=r"(r[0]),"=r"(r[1]),"=r"(r[2]),"=r"(r[3]) : "r"(addr));
}
__device__ __forceinline__ void ldm_x4_t(uint32_t* r, uint32_t addr) {
    asm volatile("ldmatrix.sync.aligned.m8n8.x4.trans.shared.b16 {%0,%1,%2,%3}, [%4];"
        : "=r"(r[0]),"=r"(r[1]),"=r"(r[2]),"=r"(r[3]) : "r"(addr));
}
__device__ __forceinline__ void mma16816(float* c, const uint32_t* a, const uint32_t* b) {
    asm volatile("mma.sync.aligned.m16n8k16.row.col.f32.bf16.bf16.f32 "
        "{%0,%1,%2,%3}, {%4,%5,%6,%7}, {%8,%9}, {%0,%1,%2,%3};"
        : "+f"(c[0]),"+f"(c[1]),"+f"(c[2]),"+f"(c[3])
        : "r"(a[0]),"r"(a[1]),"r"(a[2]),"r"(a[3]), "r"(b[0]),"r"(b[1]));
}
// ldmatrix address for a 16x16 b16 tile at (row0, byte col0) in a 128-byte-row SW128 tile
__device__ __forceinline__ uint32_t frag_addr(uint32_t base, int row0, int colb, int lane) {
    int g = lane >> 3, i = lane & 7;
    uint32_t off = (uint32_t)((row0 + i + (g & 1) * 8) * 128 + colb + (g >> 1) * 16);
    return base + SWZ128(off);
}
__device__ __forceinline__ uint32_t bf2u(__nv_bfloat162 v) {
    return *reinterpret_cast<uint32_t*>(&v);
}
// packed f32x2 helpers (small scalar GEMMs)
__device__ __forceinline__ unsigned long long pk2(float lo, float hi) {
    unsigned long long r;
    asm("mov.b64 %0, {%1, %2};" : "=l"(r) : "f"(lo), "f"(hi));
    return r;
}
__device__ __forceinline__ void fma2(unsigned long long& d, unsigned long long a, unsigned long long b) {
    asm("fma.rn.f32x2 %0, %1, %2, %0;" : "+l"(d) : "l"(a), "l"(b));
}
__device__ __forceinline__ float2 upk2(unsigned long long v) {
    float lo, hi;
    asm("mov.b64 {%0, %1}, %2;" : "=f"(lo), "=f"(hi) : "l"(v));
    return make_float2(lo, hi);
}

// ---------------- K0: prep ----------------
__global__ void k_prep(const float* __restrict__ wg, const float* __restrict__ wth,
                       const float* __restrict__ wphi, const float* __restrict__ wz,
                       const float* __restrict__ bg, const float* __restrict__ bth,
                       const float* __restrict__ bphi) {
    int idx = blockIdx.x * 256 + threadIdx.x;
    if (idx < OUTC * CC) {
        int o = idx >> 8, k = idx & 255;
        float w;
        if (o < 32)      w = wth[o * CC + k];
        else if (o < 96) w = wg[(o - 32) * CC + k];
        else             w = wphi[(o - 96) * CC + k];
        __nv_bfloat16 h = __float2bfloat16(w);
        d_Wch[idx] = h;
        d_Wcl[idx] = __float2bfloat16(w - __bfloat162float(h));
    }
    int j = idx - OUTC * CC;
    if (j >= 0 && j < CC * CG) {
        float w = wz[j];
        __nv_bfloat16 h = __float2bfloat16(w);
        d_Wzh[j] = h;
        d_Wzl[j] = __float2bfloat16(w - __bfloat162float(h));
    }
    int l = j - CC * CG;
    if (l >= 0 && l < OUTC)
        d_bc[l] = (l < 32) ? bth[l] : (l < 96 ? bg[l - 32] : bphi[l - 96]);
    if (l >= OUTC && l < OUTC + CG) {
        int c = l - OUTC;
        d_ysum[c] = 0.f; d_ysumsq[c] = 0.f;
    }
    int m = l - OUTC - CG;
    if (m >= 0 && m < BB * CI * CG) d_M[m] = 0.f;
}

// ---------------- K1: BN1 stats ----------------
__global__ void __launch_bounds__(256) k_bn1(const float* __restrict__ x,
                                             const float* __restrict__ g1,
                                             const float* __restrict__ b1) {
    int c = blockIdx.x;
    float s = 0.f, ss = 0.f;
    for (int b = 0; b < BB; b++) {
        const float4* p = (const float4*)(x + (size_t)(b * CC + c) * HW);
        for (int i = threadIdx.x; i < HW / 4; i += 256) {
            float4 v = p[i];
            s  += v.x + v.y + v.z + v.w;
            ss += v.x * v.x + v.y * v.y + v.z * v.z + v.w * v.w;
        }
    }
    for (int off = 16; off; off >>= 1) {
        s  += __shfl_down_sync(0xffffffffu, s, off);
        ss += __shfl_down_sync(0xffffffffu, ss, off);
    }
    __shared__ float rs[8], rss[8];
    int wid = threadIdx.x >> 5, lane = threadIdx.x & 31;
    if (lane == 0) { rs[wid] = s; rss[wid] = ss; }
    __syncthreads();
    if (threadIdx.x == 0) {
        float S = 0.f, SS = 0.f;
        for (int i = 0; i < 8; i++) { S += rs[i]; SS += rss[i]; }
        float n = (float)(BB * HW);
        float mean = S / n;
        float var = SS / n - mean * mean;
        float rstd = rsqrtf(var + EPSI);
        float sc = g1[c] * rstd;
        d_s1[c] = sc;
        d_t1[c] = b1[c] - mean * sc;
    }
}

// ---------------- K2: HMMA fused BN1+ReLU+conv1x1 (M=128, N=64 pix, K=256) ----------------
// smem: A_H 0..16K, A_L 16K..32K (128 rows x 128B), B_H 32K..40K, B_L 40K..48K (64 rows x 128B)
__global__ void __launch_bounds__(256) k_fconv_mma(const float* __restrict__ x) {
    __shared__ __align__(128) char smem[49152];
    uint32_t sb = smem_u32(smem);
    const uint32_t sAH = sb, sAL = sb + 16384, sBH = sb + 32768, sBL = sb + 40960;
    int tid = threadIdx.x;
    int wid = tid >> 5, lane = tid & 31;
    int wm = wid >> 1, wn = wid & 1;
    int b = blockIdx.y;
    int p0 = blockIdx.x * 64;

    float acc[2][4][4];
#pragma unroll
    for (int mt = 0; mt < 2; mt++)
#pragma unroll
        for (int nf = 0; nf < 4; nf++)
#pragma unroll
            for (int q = 0; q < 4; q++) acc[mt][nf][q] = 0.f;

    for (int kc = 0; kc < 4; kc++) {
        int k0 = kc * 64;
        __syncthreads();
        // A: weights [128 o][64 k] hi/lo
#pragma unroll
        for (int r = 0; r < 4; r++) {
            int idx = tid + r * 256;
            int row = idx >> 3, j = idx & 7;
            uint32_t sw = SWZ128((uint32_t)(row * 128 + j * 16));
            *(uint4*)(smem + (sAH - sb) + sw) = *(const uint4*)(d_Wch + row * CC + k0 + j * 8);
            *(uint4*)(smem + (sAL - sb) + sw) = *(const uint4*)(d_Wcl + row * CC + k0 + j * 8);
        }
        // B: xa [64 k][64 pix] hi/lo with fused BN1+ReLU
#pragma unroll
        for (int r = 0; r < 4; r++) {
            int idx = tid + r * 256;
            int ch = idx >> 4, pg = idx & 15;
            int c = k0 + ch;
            float4 v = *(const float4*)(x + (size_t)(b * CC + c) * HW + p0 + pg * 4);
            float sc = d_s1[c], sh = d_t1[c];
            float f0 = fmaxf(fmaf(v.x, sc, sh), 0.f);
            float f1 = fmaxf(fmaf(v.y, sc, sh), 0.f);
            float f2 = fmaxf(fmaf(v.z, sc, sh), 0.f);
            float f3 = fmaxf(fmaf(v.w, sc, sh), 0.f);
            __nv_bfloat162 h01 = __floats2bfloat162_rn(f0, f1);
            __nv_bfloat162 h23 = __floats2bfloat162_rn(f2, f3);
            __nv_bfloat162 l01 = __floats2bfloat162_rn(f0 - __bfloat162float(h01.x),
                                                       f1 - __bfloat162float(h01.y));
            __nv_bfloat162 l23 = __floats2bfloat162_rn(f2 - __bfloat162float(h23.x),
                                                       f3 - __bfloat162float(h23.y));
            uint32_t sw = SWZ128((uint32_t)(ch * 128 + pg * 8));
            *(uint2*)(smem + 32768 + sw) = make_uint2(bf2u(h01), bf2u(h23));
            *(uint2*)(smem + 40960 + sw) = make_uint2(bf2u(l01), bf2u(l23));
        }
        __syncthreads();
#pragma unroll
        for (int ks = 0; ks < 4; ks++) {
            int k16 = ks * 16;
            uint32_t bh[2][4], bl[2][4];
            ldm_x4_t(bh[0], frag_addr(sBH, k16, wn * 64, lane));
            ldm_x4_t(bh[1], frag_addr(sBH, k16, wn * 64 + 32, lane));
            ldm_x4_t(bl[0], frag_addr(sBL, k16, wn * 64, lane));
            ldm_x4_t(bl[1], frag_addr(sBL, k16, wn * 64 + 32, lane));
#pragma unroll
            for (int mt = 0; mt < 2; mt++) {
                uint32_t ah[4], al[4];
                ldm_x4(ah, frag_addr(sAH, wm * 32 + mt * 16, k16 * 2, lane));
                ldm_x4(al, frag_addr(sAL, wm * 32 + mt * 16, k16 * 2, lane));
#pragma unroll
                for (int nf = 0; nf < 4; nf++) {
                    const uint32_t* bhf = &bh[nf >> 1][(nf & 1) * 2];
                    const uint32_t* blf = &bl[nf >> 1][(nf & 1) * 2];
                    mma16816(acc[mt][nf], ah, bhf);
                    mma16816(acc[mt][nf], ah, blf);
                    mma16816(acc[mt][nf], al, bhf);
                }
            }
        }
    }
    // epilogue: direct float2 global stores (+bias)
    int g = lane >> 2, ti = lane & 3;
#pragma unroll
    for (int mt = 0; mt < 2; mt++) {
#pragma unroll
        for (int nf = 0; nf < 4; nf++) {
            int o = wm * 32 + mt * 16 + g;
            int pix = p0 + wn * 32 + nf * 8 + ti * 2;
            float b0 = d_bc[o], b8 = d_bc[o + 8];
            float* d0 = d_conv + (size_t)(b * OUTC + o) * HW + pix;
            float* d1 = d_conv + (size_t)(b * OUTC + o + 8) * HW + pix;
            *(float2*)d0 = make_float2(acc[mt][nf][0] + b0, acc[mt][nf][1] + b0);
            *(float2*)d1 = make_float2(acc[mt][nf][2] + b8, acc[mt][nf][3] + b8);
        }
    }
}

// ---------------- K3: 2x2 maxpool ----------------
__global__ void k_pool() {
    int idx = blockIdx.x * 256 + threadIdx.x;
    if (idx >= BB * 96 * 392) return;
    int b = idx / (96 * 392);
    int r = idx % (96 * 392);
    int ch = r / 392;
    int q = r % 392;
    int phh = q / 14, pw4 = q % 14;
    const float* src = d_conv + (size_t)(b * OUTC + 32 + ch) * HW + phh * 112 + pw4 * 4;
    float4 r0 = *(const float4*)src;
    float4 r1 = *(const float4*)(src + 56);
    float o0 = fmaxf(fmaxf(r0.x, r0.y), fmaxf(r1.x, r1.y));
    float o1 = fmaxf(fmaxf(r0.z, r0.w), fmaxf(r1.z, r1.w));
    int p = phh * 28 + pw4 * 2;
    if (ch < 64) *(float2*)(d_gpool + (b * CG + ch) * NP + p) = make_float2(o0, o1);
    else         *(float2*)(d_phipool + (b * CI + (ch - 64)) * NP + p) = make_float2(o0, o1);
}

// ---------------- K4: M[b] = phi_pool @ g_pool^T ----------------
__global__ void __launch_bounds__(512) k_M() {
    int b = blockIdx.y;
    int m0 = blockIdx.x * 112;
    __shared__ float Ps[CI][113];
    __shared__ float Gs[CG][113];
    int tid = threadIdx.x;
    for (int j = tid; j < CI * 112; j += 512) {
        int i = j / 112, mm = j % 112;
        Ps[i][mm] = d_phipool[(b * CI + i) * NP + m0 + mm];
    }
    for (int j = tid; j < CG * 112; j += 512) {
        int i = j / 112, mm = j % 112;
        Gs[i][mm] = d_gpool[(b * CG + i) * NP + m0 + mm];
    }
    __syncthreads();
#pragma unroll
    for (int q = 0; q < 4; q++) {
        int o = tid + q * 512;
        int i = o >> 6, c = o & 63;
        float acc = 0.f;
#pragma unroll 8
        for (int mm = 0; mm < 112; mm++) acc = fmaf(Ps[i][mm], Gs[c][mm], acc);
        atomicAdd(&d_M[(b * CI + i) * CG + c], acc);
    }
}

// ---------------- K5: y = (M/Np)^T @ theta + BN2-stat accumulation ----------------
__global__ void __launch_bounds__(256) k_Y() {
    int b = blockIdx.y;
    int p0 = blockIdx.x * 64;
    __shared__ float Ms[CI * CG];
    __shared__ float Ts[CI * 64];
    __shared__ float bs[CG], bss[CG];
    int tid = threadIdx.x;
    const float invNp = 1.0f / (float)NP;
    for (int j = tid; j < CI * CG; j += 256) Ms[j] = d_M[b * CI * CG + j] * invNp;
    for (int j = tid; j < CI * 64; j += 256) {
        int i = j >> 6, col = j & 63;
        Ts[j] = d_conv[(size_t)(b * OUTC + i) * HW + p0 + col];
    }
    if (tid < CG) { bs[tid] = 0.f; bss[tid] = 0.f; }
    __syncthreads();
    int tx = tid & 15, ty = tid >> 4;
    unsigned long long acc[4][2];
#pragma unroll
    for (int ci = 0; ci < 4; ci++) { acc[ci][0] = 0ull; acc[ci][1] = 0ull; }
#pragma unroll 8
    for (int i = 0; i < CI; i++) {
        float4 mv = *(float4*)&Ms[i * CG + ty * 4];
        float4 tv = *(float4*)&Ts[i * 64 + tx * 4];
        unsigned long long t01 = pk2(tv.x, tv.y), t23 = pk2(tv.z, tv.w);
        float mm[4] = {mv.x, mv.y, mv.z, mv.w};
#pragma unroll
        for (int ci = 0; ci < 4; ci++) {
            unsigned long long md = pk2(mm[ci], mm[ci]);
            fma2(acc[ci][0], md, t01);
            fma2(acc[ci][1], md, t23);
        }
    }
#pragma unroll
    for (int ci = 0; ci < 4; ci++) {
        int cg = ty * 4 + ci;
        float2 a = upk2(acc[ci][0]), c2 = upk2(acc[ci][1]);
        *(float4*)(d_y + (size_t)(b * CG + cg) * HW + p0 + tx * 4) =
            make_float4(a.x, a.y, c2.x, c2.y);
        atomicAdd(&bs[cg], a.x + a.y + c2.x + c2.y);
        atomicAdd(&bss[cg], a.x * a.x + a.y * a.y + c2.x * c2.x + c2.y * c2.y);
    }
    __syncthreads();
    if (tid < CG) {
        atomicAdd(&d_ysum[tid], bs[tid]);
        atomicAdd(&d_ysumsq[tid], bss[tid]);
    }
}

// ---------------- K5b: BN2 scale/shift ----------------
__global__ void k_bn2(const float* __restrict__ g2, const float* __restrict__ b2) {
    int c = threadIdx.x;
    if (c < CG) {
        float n = (float)(BB * HW);
        float mean = d_ysum[c] / n;
        float var = d_ysumsq[c] / n - mean * mean;
        float rstd = rsqrtf(var + EPSI);
        float sc = g2[c] * rstd;
        d_s2[c] = sc;
        d_t2[c] = b2[c] - mean * sc;
    }
}

// ---------------- K6: HMMA BN2+ReLU+conv(64->256)+bias+identity ----------------
// dynamic smem: A_H 0..32K (256 rows x 128B), A_L 32K..64K, B_H 64K..72K, B_L 72K..80K
#define Z_SMEM 81920
__global__ void __launch_bounds__(256) k_final_mma(const float* __restrict__ x,
                                                   const float* __restrict__ bz,
                                                   float* __restrict__ out) {
    extern __shared__ __align__(128) char smem[];
    uint32_t sb = smem_u32(smem);
    const uint32_t sAH = sb, sAL = sb + 32768, sBH = sb + 65536, sBL = sb + 73728;
    int tid = threadIdx.x;
    int wid = tid >> 5, lane = tid & 31;
    int wm = wid >> 1, wn = wid & 1;
    int b = blockIdx.y;
    int p0 = blockIdx.x * 64;

    // A: w_z [256 o][64 k] hi/lo
#pragma unroll
    for (int r = 0; r < 8; r++) {
        int idx = tid + r * 256;
        int row = idx >> 3, j = idx & 7;
        uint32_t sw = SWZ128((uint32_t)(row * 128 + j * 16));
        *(uint4*)(smem + sw)         = *(const uint4*)(d_Wzh + row * CG + j * 8);
        *(uint4*)(smem + 32768 + sw) = *(const uint4*)(d_Wzl + row * CG + j * 8);
    }
    // B: normalized-relu y [64 k][64 pix] hi/lo
#pragma unroll
    for (int r = 0; r < 4; r++) {
        int idx = tid + r * 256;
        int ch = idx >> 4, pg = idx & 15;
        float4 v = *(const float4*)(d_y + (size_t)(b * CG + ch) * HW + p0 + pg * 4);
        float sc = d_s2[ch], sh = d_t2[ch];
        float f0 = fmaxf(fmaf(v.x, sc, sh), 0.f);
        float f1 = fmaxf(fmaf(v.y, sc, sh), 0.f);
        float f2 = fmaxf(fmaf(v.z, sc, sh), 0.f);
        float f3 = fmaxf(fmaf(v.w, sc, sh), 0.f);
        __nv_bfloat162 h01 = __floats2bfloat162_rn(f0, f1);
        __nv_bfloat162 h23 = __floats2bfloat162_rn(f2, f3);
        __nv_bfloat162 l01 = __floats2bfloat162_rn(f0 - __bfloat162float(h01.x),
                                                   f1 - __bfloat162float(h01.y));
        __nv_bfloat162 l23 = __floats2bfloat162_rn(f2 - __bfloat162float(h23.x),
                                                   f3 - __bfloat162float(h23.y));
        uint32_t sw = SWZ128((uint32_t)(ch * 128 + pg * 8));
        *(uint2*)(smem + 65536 + sw) = make_uint2(bf2u(h01), bf2u(h23));
        *(uint2*)(smem + 73728 + sw) = make_uint2(bf2u(l01), bf2u(l23));
    }
    __syncthreads();

    float acc[4][4][4];
#pragma unroll
    for (int mt = 0; mt < 4; mt++)
#pragma unroll
        for (int nf = 0; nf < 4; nf++)
#pragma unroll
            for (int q = 0; q < 4; q++) acc[mt][nf][q] = 0.f;

#pragma unroll
    for (int ks = 0; ks < 4; ks++) {
        int k16 = ks * 16;
        uint32_t bh[2][4], bl[2][4];
        ldm_x4_t(bh[0], frag_addr(sBH, k16, wn * 64, lane));
        ldm_x4_t(bh[1], frag_addr(sBH, k16, wn * 64 + 32, lane));
        ldm_x4_t(bl[0], frag_addr(sBL, k16, wn * 64, lane));
        ldm_x4_t(bl[1], frag_addr(sBL, k16, wn * 64 + 32, lane));
#pragma unroll
        for (int mt = 0; mt < 4; mt++) {
            uint32_t ah[4], al[4];
            ldm_x4(ah, frag_addr(sAH, wm * 64 + mt * 16, k16 * 2, lane));
            ldm_x4(al, frag_addr(sAL, wm * 64 + mt * 16, k16 * 2, lane));
#pragma unroll
            for (int nf = 0; nf < 4; nf++) {
                const uint32_t* bhf = &bh[nf >> 1][(nf & 1) * 2];
                const uint32_t* blf = &bl[nf >> 1][(nf & 1) * 2];
                mma16816(acc[mt][nf], ah, bhf);
                mma16816(acc[mt][nf], ah, blf);
                mma16816(acc[mt][nf], al, bhf);
            }
        }
    }
    // epilogue: + bias + identity
    int g = lane >> 2, ti = lane & 3;
#pragma unroll
    for (int mt = 0; mt < 4; mt++) {
#pragma unroll
        for (int nf = 0; nf < 4; nf++) {
            int o = wm * 64 + mt * 16 + g;
            int pix = p0 + wn * 32 + nf * 8 + ti * 2;
            float b0 = __ldg(&bz[o]), b8 = __ldg(&bz[o + 8]);
            const float* x0 = x + (size_t)(b * CC + o) * HW + pix;
            const float* x1 = x + (size_t)(b * CC + o + 8) * HW + pix;
            float2 i0 = *(const float2*)x0;
            float2 i1 = *(const float2*)x1;
            float* d0 = out + (size_t)(b * CC + o) * HW + pix;
            float* d1 = out + (size_t)(b * CC + o + 8) * HW + pix;
            *(float2*)d0 = make_float2(acc[mt][nf][0] + b0 + i0.x, acc[mt][nf][1] + b0 + i0.y);
            *(float2*)d1 = make_float2(acc[mt][nf][2] + b8 + i1.x, acc[mt][nf][3] + b8 + i1.y);
        }
    }
}

// ---------------- host ----------------
extern "C" void kernel_launch(void* const* d_in, const int* in_sizes, int n_in,
                              void* d_out, int out_size) {
    const float* x   = (const float*)d_in[0];
    const float* g1  = (const float*)d_in[1];
    const float* b1  = (const float*)d_in[2];
    const float* wg  = (const float*)d_in[3];
    const float* bg  = (const float*)d_in[4];
    const float* wth = (const float*)d_in[5];
    const float* bth = (const float*)d_in[6];
    const float* wph = (const float*)d_in[7];
    const float* bph = (const float*)d_in[8];
    const float* g2  = (const float*)d_in[9];
    const float* b2  = (const float*)d_in[10];
    const float* wz  = (const float*)d_in[11];
    const float* bz  = (const float*)d_in[12];
    float* out = (float*)d_out;

    static bool attr_set = false;
    if (!attr_set) {
        cudaFuncSetAttribute(k_final_mma, cudaFuncAttributeMaxDynamicSharedMemorySize, Z_SMEM);
        attr_set = true;
    }

    int prep_elems = OUTC * CC + CC * CG + OUTC + CG + BB * CI * CG;
    k_prep<<<(prep_elems + 255) / 256, 256>>>(wg, wth, wph, wz, bg, bth, bph);
    k_bn1<<<CC, 256>>>(x, g1, b1);
    {
        dim3 g(HW / 64, BB);
        k_fconv_mma<<<g, 256>>>(x);
    }
    k_pool<<<(BB * 96 * 392 + 255) / 256, 256>>>();
    {
        dim3 g(7, BB);
        k_M<<<g, 512>>>();
    }
    {
        dim3 g(HW / 64, BB);
        k_Y<<<g, 256>>>();
    }
    k_bn2<<<1, 64>>>(g2, b2);
    {
        dim3 g(HW / 64, BB);
        k_final_mma<<<g, 256, Z_SMEM>>>(x, bz, out);
    }
}